// round 1
// baseline (speedup 1.0000x reference)
#include <cuda_runtime.h>
#include <cstdint>

#define NMAX 100000
#define EMAX 1000000
#define SA 132   // smem A row stride (floats): keeps LDS.128 16B-aligned, breaks STS conflicts

// -------- persistent device scratch (no allocations allowed) --------
__device__ float4 g_hs [NMAX * 16];   // scaled h (h * out_norm), 25.6 MB
__device__ float4 g_agg[NMAX * 16];   // edge aggregation buffer
__device__ float4 g_h  [NMAX * 16];   // current layer activations
__device__ float4 g_hf [NMAX * 16];   // jumping-knowledge accumulator
__device__ float  g_onorm[NMAX];      // out-degree -> rsqrt norm (in place)
__device__ float  g_inorm[NMAX];      // in-degree  -> rsqrt norm (in place)

// -------- degree / norm kernels --------
__global__ void zero_deg_kernel(int n) {
    int i = blockIdx.x * blockDim.x + threadIdx.x;
    if (i < n) { g_onorm[i] = 0.f; g_inorm[i] = 0.f; }
}

__global__ void deg_kernel(const int* __restrict__ src, const int* __restrict__ dst, int e) {
    int i = blockIdx.x * blockDim.x + threadIdx.x;
    if (i < e) {
        atomicAdd(&g_onorm[src[i]], 1.0f);
        atomicAdd(&g_inorm[dst[i]], 1.0f);
    }
}

__global__ void norm_kernel(int n) {
    int i = blockIdx.x * blockDim.x + threadIdx.x;
    if (i < n) {
        g_onorm[i] = rsqrtf(fmaxf(g_onorm[i], 1.0f));
        g_inorm[i] = rsqrtf(fmaxf(g_inorm[i], 1.0f));
    }
}

// -------- per-layer prep: hs = h * out_norm ; agg = 0 --------
__global__ void prep_kernel(const float4* __restrict__ h_ext, int use_ext, int n16) {
    int i = blockIdx.x * blockDim.x + threadIdx.x;
    if (i >= n16) return;
    const float4* h = use_ext ? h_ext : g_h;
    float s = g_onorm[i >> 4];
    float4 v = h[i];
    g_hs[i]  = make_float4(v.x * s, v.y * s, v.z * s, v.w * s);
    g_agg[i] = make_float4(0.f, 0.f, 0.f, 0.f);
}

// -------- edge scatter: agg[dst] += hs[src], 16 lanes per edge, vector red --------
__global__ void edge_kernel(const int* __restrict__ src, const int* __restrict__ dst, int e16) {
    int i = blockIdx.x * blockDim.x + threadIdx.x;
    if (i >= e16) return;
    int e = i >> 4;
    int q = i & 15;
    int s = __ldg(src + e);
    int d = __ldg(dst + e);
    float4 v = g_hs[s * 16 + q];
    float4* p = &g_agg[d * 16 + q];
    asm volatile("red.global.add.v4.f32 [%0], {%1, %2, %3, %4};"
                 :: "l"(p), "f"(v.x), "f"(v.y), "f"(v.z), "f"(v.w)
                 : "memory");
}

// -------- fused layer GEMM: t = [agg*in_norm | h] @ [convW; resW] + b ; LN ; relu ;
//          h <- t ; h_final (+)= t.  Tile 128 rows x 64 cols, K = 128. --------
__global__ __launch_bounds__(256, 2)
void fused_kernel(const float* __restrict__ h_ext, int use_ext,
                  const float* __restrict__ convW, const float* __restrict__ resW,
                  const float* __restrict__ conv_b, const float* __restrict__ res_b,
                  const float* __restrict__ ln_g,  const float* __restrict__ ln_b,
                  int n, int first)
{
    extern __shared__ float sm[];
    float* As = sm;               // [128][SA], k-major (transposed)
    float* Ws = sm + 128 * SA;    // [128][64]
    const float* agg  = (const float*)g_agg;
    const float* h_in = use_ext ? h_ext : (const float*)g_h;

    int t = threadIdx.x;
    int base = blockIdx.x * 128;

    // load combined weight [convW ; resW] -> Ws[k][d]
    for (int i = t; i < 2048; i += 256) {
        int k = i >> 4, c4 = i & 15;
        const float* wsrc = (k < 64) ? (convW + k * 64) : (resW + (k - 64) * 64);
        *(float4*)(Ws + k * 64 + c4 * 4) = *(const float4*)(wsrc + c4 * 4);
    }
    // A first half: agg * in_norm, transposed into As[k][r]
    for (int i = t; i < 2048; i += 256) {
        int r = i >> 4, k4 = i & 15;
        int node = base + r;
        float4 v = make_float4(0.f, 0.f, 0.f, 0.f);
        float nn = 0.f;
        if (node < n) { v = *(const float4*)(agg + node * 64 + k4 * 4); nn = g_inorm[node]; }
        int k = k4 * 4;
        As[(k + 0) * SA + r] = v.x * nn;
        As[(k + 1) * SA + r] = v.y * nn;
        As[(k + 2) * SA + r] = v.z * nn;
        As[(k + 3) * SA + r] = v.w * nn;
    }
    // A second half: h
    for (int i = t; i < 2048; i += 256) {
        int r = i >> 4, k4 = i & 15;
        int node = base + r;
        float4 v = make_float4(0.f, 0.f, 0.f, 0.f);
        if (node < n) v = *(const float4*)(h_in + node * 64 + k4 * 4);
        int k = 64 + k4 * 4;
        As[(k + 0) * SA + r] = v.x;
        As[(k + 1) * SA + r] = v.y;
        As[(k + 2) * SA + r] = v.z;
        As[(k + 3) * SA + r] = v.w;
    }
    __syncthreads();

    int rg = t >> 3;      // 0..31 : rows rg*4 .. rg*4+3
    int cg = t & 7;       // 0..7  : cols cg*8 .. cg*8+7
    float acc[4][8];
#pragma unroll
    for (int r = 0; r < 4; r++)
#pragma unroll
        for (int c = 0; c < 8; c++) acc[r][c] = 0.f;

#pragma unroll 8
    for (int k = 0; k < 128; k++) {
        float4 a  = *(const float4*)(As + k * SA + rg * 4);
        float4 w0 = *(const float4*)(Ws + k * 64 + cg * 8);
        float4 w1 = *(const float4*)(Ws + k * 64 + cg * 8 + 4);
        float av[4] = {a.x, a.y, a.z, a.w};
        float wv[8] = {w0.x, w0.y, w0.z, w0.w, w1.x, w1.y, w1.z, w1.w};
#pragma unroll
        for (int r = 0; r < 4; r++)
#pragma unroll
            for (int c = 0; c < 8; c++)
                acc[r][c] += av[r] * wv[c];
    }

    // epilogue: bias, LayerNorm across 8 lanes (cg dim), relu, write h and h_final
    int col0 = cg * 8;
    float bb[8], gg[8], lb[8];
#pragma unroll
    for (int c = 0; c < 8; c++) {
        bb[c] = conv_b[col0 + c] + res_b[col0 + c];
        gg[c] = ln_g[col0 + c];
        lb[c] = ln_b[col0 + c];
    }
    float* hout = (float*)g_h;
    float* hf   = (float*)g_hf;

#pragma unroll
    for (int r = 0; r < 4; r++) {
        float v[8]; float s = 0.f, sq = 0.f;
#pragma unroll
        for (int c = 0; c < 8; c++) {
            v[c] = acc[r][c] + bb[c];
            s += v[c]; sq += v[c] * v[c];
        }
#pragma unroll
        for (int m = 1; m < 8; m <<= 1) {
            s  += __shfl_xor_sync(0xffffffffu, s,  m);
            sq += __shfl_xor_sync(0xffffffffu, sq, m);
        }
        float mu  = s * (1.f / 64.f);
        float var = sq * (1.f / 64.f) - mu * mu;
        float inv = rsqrtf(var + 1e-5f);
        int node = base + rg * 4 + r;
        if (node < n) {
            float o[8];
#pragma unroll
            for (int c = 0; c < 8; c++) {
                float x = (v[c] - mu) * inv * gg[c] + lb[c];
                o[c] = fmaxf(x, 0.f);
            }
            float4 o0 = make_float4(o[0], o[1], o[2], o[3]);
            float4 o1 = make_float4(o[4], o[5], o[6], o[7]);
            *(float4*)(hout + node * 64 + col0)     = o0;
            *(float4*)(hout + node * 64 + col0 + 4) = o1;
            float4* fp = (float4*)(hf + node * 64 + col0);
            if (first) {
                fp[0] = o0; fp[1] = o1;
            } else {
                float4 a0 = fp[0], a1 = fp[1];
                a0.x += o0.x; a0.y += o0.y; a0.z += o0.z; a0.w += o0.w;
                a1.x += o1.x; a1.y += o1.y; a1.z += o1.z; a1.w += o1.w;
                fp[0] = a0; fp[1] = a1;
            }
        }
    }
}

// -------- final prediction GEMM: out = h_final @ predW + pred_b (K = 64) --------
__global__ __launch_bounds__(256, 2)
void pred_kernel(const float* __restrict__ predW, const float* __restrict__ pred_b,
                 float* __restrict__ out, int n)
{
    extern __shared__ float sm[];
    float* As = sm;              // [64][SA]
    float* Ws = sm + 64 * SA;    // [64][64]
    const float* hfin = (const float*)g_hf;

    int t = threadIdx.x;
    int base = blockIdx.x * 128;

    for (int i = t; i < 1024; i += 256) {
        int k = i >> 4, c4 = i & 15;
        *(float4*)(Ws + k * 64 + c4 * 4) = *(const float4*)(predW + k * 64 + c4 * 4);
    }
    for (int i = t; i < 2048; i += 256) {
        int r = i >> 4, k4 = i & 15;
        int node = base + r;
        float4 v = make_float4(0.f, 0.f, 0.f, 0.f);
        if (node < n) v = *(const float4*)(hfin + node * 64 + k4 * 4);
        int k = k4 * 4;
        As[(k + 0) * SA + r] = v.x;
        As[(k + 1) * SA + r] = v.y;
        As[(k + 2) * SA + r] = v.z;
        As[(k + 3) * SA + r] = v.w;
    }
    __syncthreads();

    int rg = t >> 3, cg = t & 7;
    float acc[4][8];
#pragma unroll
    for (int r = 0; r < 4; r++)
#pragma unroll
        for (int c = 0; c < 8; c++) acc[r][c] = 0.f;

#pragma unroll 8
    for (int k = 0; k < 64; k++) {
        float4 a  = *(const float4*)(As + k * SA + rg * 4);
        float4 w0 = *(const float4*)(Ws + k * 64 + cg * 8);
        float4 w1 = *(const float4*)(Ws + k * 64 + cg * 8 + 4);
        float av[4] = {a.x, a.y, a.z, a.w};
        float wv[8] = {w0.x, w0.y, w0.z, w0.w, w1.x, w1.y, w1.z, w1.w};
#pragma unroll
        for (int r = 0; r < 4; r++)
#pragma unroll
            for (int c = 0; c < 8; c++)
                acc[r][c] += av[r] * wv[c];
    }

    int col0 = cg * 8;
    float bb[8];
#pragma unroll
    for (int c = 0; c < 8; c++) bb[c] = pred_b[col0 + c];

#pragma unroll
    for (int r = 0; r < 4; r++) {
        int node = base + rg * 4 + r;
        if (node < n) {
            float4 o0 = make_float4(acc[r][0] + bb[0], acc[r][1] + bb[1],
                                    acc[r][2] + bb[2], acc[r][3] + bb[3]);
            float4 o1 = make_float4(acc[r][4] + bb[4], acc[r][5] + bb[5],
                                    acc[r][6] + bb[6], acc[r][7] + bb[7]);
            *(float4*)(out + node * 64 + col0)     = o0;
            *(float4*)(out + node * 64 + col0 + 4) = o1;
        }
    }
}

// -------- host entry --------
extern "C" void kernel_launch(void* const* d_in, const int* in_sizes, int n_in,
                              void* d_out, int out_size)
{
    const float* feats  = (const float*)d_in[0];
    const int*   src    = (const int*)  d_in[1];
    const int*   dst    = (const int*)  d_in[2];
    const float* convW  = (const float*)d_in[3];   // [3][64][64]
    const float* conv_b = (const float*)d_in[4];   // [3][64]
    const float* resW   = (const float*)d_in[5];
    const float* res_b  = (const float*)d_in[6];
    const float* ln_g   = (const float*)d_in[7];
    const float* ln_b   = (const float*)d_in[8];
    const float* predW  = (const float*)d_in[9];
    const float* pred_b = (const float*)d_in[10];

    int n = in_sizes[0] / 64;
    int e = in_sizes[1];

    const int smem_fused = (128 * SA + 128 * 64) * 4;  // 100352 B
    const int smem_pred  = (64 * SA + 64 * 64) * 4;    //  50176 B
    cudaFuncSetAttribute(fused_kernel, cudaFuncAttributeMaxDynamicSharedMemorySize, smem_fused);
    cudaFuncSetAttribute(pred_kernel,  cudaFuncAttributeMaxDynamicSharedMemorySize, smem_pred);

    zero_deg_kernel<<<(n + 255) / 256, 256>>>(n);
    deg_kernel<<<(e + 255) / 256, 256>>>(src, dst, e);
    norm_kernel<<<(n + 255) / 256, 256>>>(n);

    int n16 = n * 16;
    int e16 = e * 16;
    int gb = (n + 127) / 128;

    for (int l = 0; l < 3; l++) {
        int use_ext = (l == 0) ? 1 : 0;
        prep_kernel<<<(n16 + 255) / 256, 256>>>((const float4*)feats, use_ext, n16);
        edge_kernel<<<(e16 + 255) / 256, 256>>>(src, dst, e16);
        fused_kernel<<<gb, 256, smem_fused>>>(feats, use_ext,
                                              convW + l * 4096, resW + l * 4096,
                                              conv_b + l * 64, res_b + l * 64,
                                              ln_g + l * 64, ln_b + l * 64,
                                              n, (l == 0) ? 1 : 0);
    }
    pred_kernel<<<gb, 256, smem_pred>>>(predW, pred_b, (float*)d_out, n);
}